// round 16
// baseline (speedup 1.0000x reference)
#include <cuda_runtime.h>
#include <cuda_bf16.h>

// Single persistent kernel: stable 4-class counting sort + margin adjust +
// fused mean-NLL loss. Output: [data[N,4] | labels[N] | loss] float32.
//
// R16 = R15 + 2-tile super-tile phase 2 at launch_bounds(256,4):
//   ranks TWO tiles per iteration, then issues 8 independent coalesced
//   LDG.128 (MLP=8/thread) before processing — outstanding loads per SMSP
//   rises 48 -> 64 (the quantity that has tracked throughput all session).

constexpr int TPB = 256;
constexpr int WPB = 8;
constexpr int TILE = 1024;             // rows per tile
constexpr int T_PB_MAX = 14;
constexpr int MAX_BLOCKS_G = 4096;
constexpr int RESIDENT_BPSM = 4;

__device__ int4 g_blockHist[MAX_BLOCKS_G];
__device__ int4 g_blockOff[MAX_BLOCKS_G];
__device__ int4 g_classBase;
__device__ double g_loss;
__device__ unsigned g_histDone;
__device__ unsigned g_scatDone;
__device__ volatile unsigned g_flag;

static __device__ __forceinline__ int4 add4(int4 a, int4 b) {
    return make_int4(a.x + b.x, a.y + b.y, a.z + b.z, a.w + b.w);
}

// rank 4 consecutive rows (packed classes in 'byte') against warp-adjusted
// class bases; returns (dest<<2)|class per row
static __device__ __forceinline__ int4 rankRows(unsigned byte, int b0, int b1,
                                                int b2, int b3, int lane) {
    int c0 = byte & 3, c1 = (byte >> 2) & 3;
    int c2 = (byte >> 4) & 3, c3 = (byte >> 6) & 3;
    unsigned cnt = (1u << (8 * c0)) + (1u << (8 * c1)) +
                   (1u << (8 * c2)) + (1u << (8 * c3));
    unsigned incl = cnt;
#pragma unroll
    for (int off = 1; off < 32; off <<= 1) {
        unsigned v = __shfl_up_sync(0xffffffffu, incl, off);
        if (lane >= off) incl += v;
    }
    unsigned excl = incl - cnt;
    b0 += excl & 0xff;
    b1 += (excl >> 8) & 0xff;
    b2 += (excl >> 16) & 0xff;
    b3 += (excl >> 24) & 0xff;

    int4 dpk;
    int* dv = &dpk.x;
#pragma unroll
    for (int k = 0; k < 4; ++k) {
        int c = (k == 0) ? c0 : (k == 1) ? c1 : (k == 2) ? c2 : c3;
        int dest;
        if (c == 0) dest = b0++;
        else if (c == 1) dest = b1++;
        else if (c == 2) dest = b2++;
        else dest = b3++;
        dv[k] = (dest << 2) | c;
    }
    return dpk;
}

// margin-adjust + loss + streaming scatter store for one row
static __device__ __forceinline__ float doRow(float4 r, int dpacked,
                                              float4* __restrict__ outData) {
    int c = dpacked & 3;
    int dest = dpacked >> 2;
    float v = (c == 0) ? r.x : (c == 1) ? r.y : (c == 2) ? r.z : r.w;
    float adj = (v > 0.0f) ? v * (1.0f / 4.00001f) - 0.5f
                           : v * 4.00001f - 0.5f;
    if (c == 0) r.x = adj; else if (c == 1) r.y = adj;
    else if (c == 2) r.z = adj; else r.w = adj;
    // no max-subtraction: inputs ~N(0,1) -> exp cannot overflow
    float e = __expf(r.x) + __expf(r.y) + __expf(r.z) + __expf(r.w);
    __stcs(outData + dest, r);
    return __logf(e) - adj;                      // -log p[true]
}

__global__ void __launch_bounds__(TPB, RESIDENT_BPSM)
fusedKernel(const float* __restrict__ data, const int* __restrict__ label,
            float* __restrict__ outData, float* __restrict__ outLabel,
            float* __restrict__ outLoss, int n, int numTiles) {
    __shared__ unsigned char sClass[T_PB_MAX][TILE / 4];  // 2 bits/row packed
    __shared__ int4 sWarpHist[T_PB_MAX][WPB];
    __shared__ int4 sTileHist[T_PB_MAX];
    __shared__ int sDest[2 * TILE];                       // (dest<<2)|class
    __shared__ float warpLoss[WPB];
    __shared__ bool sScan;

    int tid = threadIdx.x;
    int w = tid >> 5;
    int lane = tid & 31;

    int t0 = (int)(((long long)blockIdx.x * numTiles) / gridDim.x);
    int t1 = (int)(((long long)(blockIdx.x + 1) * numTiles) / gridDim.x);
    int nt = t1 - t0;
    int nv4 = n >> 2;

    // ---------------- Phase 1: labels -> smem classes + hists ---------------
    for (int s = 0; s < nt; ++s) {
        int tile = t0 + s;
        int vi = (tile * (TILE / 4)) + tid;          // rows 4vi..4vi+3
        int c0 = 0, c1 = 0, c2 = 0, c3 = 0;
        unsigned byte = 0;
        if (vi < nv4) {
            int4 L = __ldcs(reinterpret_cast<const int4*>(label) + vi);
            byte = (unsigned)(L.x | (L.y << 2) | (L.z << 4) | (L.w << 6));
            c0 = (L.x == 0) + (L.y == 0) + (L.z == 0) + (L.w == 0);
            c1 = (L.x == 1) + (L.y == 1) + (L.z == 1) + (L.w == 1);
            c2 = (L.x == 2) + (L.y == 2) + (L.z == 2) + (L.w == 2);
            c3 = (L.x == 3) + (L.y == 3) + (L.z == 3) + (L.w == 3);
        }
        sClass[s][tid] = (unsigned char)byte;
#pragma unroll
        for (int off = 16; off > 0; off >>= 1) {
            c0 += __shfl_down_sync(0xffffffffu, c0, off);
            c1 += __shfl_down_sync(0xffffffffu, c1, off);
            c2 += __shfl_down_sync(0xffffffffu, c2, off);
            c3 += __shfl_down_sync(0xffffffffu, c3, off);
        }
        if (lane == 0) sWarpHist[s][w] = make_int4(c0, c1, c2, c3);
    }
    __syncthreads();
    if (tid < nt) {                                  // per-tile totals
        int4 sum = make_int4(0, 0, 0, 0);
#pragma unroll
        for (int ww = 0; ww < WPB; ++ww) sum = add4(sum, sWarpHist[tid][ww]);
        sTileHist[tid] = sum;
    }
    __syncthreads();
    if (tid == 0) {                                  // per-BLOCK total
        int4 bsum = make_int4(0, 0, 0, 0);
        for (int s = 0; s < nt; ++s) bsum = add4(bsum, sTileHist[s]);
        g_blockHist[blockIdx.x] = bsum;
    }

    // ---------------- Grid sync + block-level scan by last block ------------
    __threadfence();
    if (tid == 0) {
        unsigned t = atomicAdd(&g_histDone, 1u);
        sScan = (t == gridDim.x - 1);
        if (sScan) g_histDone = 0;                   // reset for graph replay
    }
    __syncthreads();

    if (sScan) {
        __shared__ int4 ss[TPB];
        int numB = gridDim.x;
        int chunk = (numB + TPB - 1) / TPB;
        int start = tid * chunk;
        int end = min(start + chunk, numB);
        int4 s = make_int4(0, 0, 0, 0);
        for (int j = start; j < end; ++j) s = add4(s, g_blockHist[j]);
        ss[tid] = s;
        __syncthreads();
        for (int off = 1; off < TPB; off <<= 1) {
            int4 v = ss[tid];
            if (tid >= off) v = add4(v, ss[tid - off]);
            __syncthreads();
            ss[tid] = v;
            __syncthreads();
        }
        int4 incl = ss[tid];
        int4 tot = ss[TPB - 1];
        int4 run;
        run.x = (incl.x - s.x);
        run.y = (incl.y - s.y) + tot.x;
        run.z = (incl.z - s.z) + tot.x + tot.y;
        run.w = (incl.w - s.w) + tot.x + tot.y + tot.z;
        for (int j = start; j < end; ++j) {
            int4 h = g_blockHist[j];
            g_blockOff[j] = run;
            run = add4(run, h);
        }
        if (tid == 0) {
            g_classBase = make_int4(0, tot.x, tot.x + tot.y,
                                    tot.x + tot.y + tot.z);
            g_loss = 0.0;
        }
        __syncthreads();
        __threadfence();
        if (tid == 0) g_flag = 1;                    // release
    } else {
        if (tid == 0) {
            while (g_flag == 0) __nanosleep(64);
        }
        __syncthreads();
        __threadfence();                             // acquire
    }

    // ---------------- Phase 2: 2-tile super-tile scatter --------------------
    int4 cb = g_classBase;
    int4 cur = g_blockOff[blockIdx.x];               // running tile offsets
    float lsum = 0.0f;
    const float4* dp = reinterpret_cast<const float4*>(data);
    float4* op = reinterpret_cast<float4*>(outData);

    for (int s = 0; s < nt; s += 2) {
        bool hasB = (s + 1 < nt);
        int tileA = t0 + s;
        int4 curB = hasB ? add4(cur, sTileHist[s]) : cur;

        // ---- Stage A: rank both tiles -----------------------------------
        {
            int a0 = cur.x, a1 = cur.y, a2 = cur.z, a3 = cur.w;
            for (int ww = 0; ww < w; ++ww) {
                int4 h = sWarpHist[s][ww];
                a0 += h.x; a1 += h.y; a2 += h.z; a3 += h.w;
            }
            reinterpret_cast<int4*>(sDest)[tid] =
                rankRows(sClass[s][tid], a0, a1, a2, a3, lane);

            if (hasB) {
                int b0 = curB.x, b1 = curB.y, b2 = curB.z, b3 = curB.w;
                for (int ww = 0; ww < w; ++ww) {
                    int4 h = sWarpHist[s + 1][ww];
                    b0 += h.x; b1 += h.y; b2 += h.z; b3 += h.w;
                }
                reinterpret_cast<int4*>(sDest)[TPB + tid] =
                    rankRows(sClass[s + 1][tid], b0, b1, b2, b3, lane);
            }
        }
        __syncwarp();

        // ---- Stage B: 8 independent coalesced loads (MLP=8) + process ----
        {
            int rowT = w * 128 + lane;
            int iA = tileA * TILE + rowT;
            int iB = iA + TILE;

            float4 a0, a1, a2, a3, b0, b1, b2, b3;
            a0 = a1 = a2 = a3 = make_float4(0.f, 0.f, 0.f, 0.f);
            b0 = b1 = b2 = b3 = a0;
            if (iA < n)      a0 = __ldcs(dp + iA);
            if (iA + 32 < n) a1 = __ldcs(dp + iA + 32);
            if (iA + 64 < n) a2 = __ldcs(dp + iA + 64);
            if (iA + 96 < n) a3 = __ldcs(dp + iA + 96);
            if (hasB) {
                if (iB < n)      b0 = __ldcs(dp + iB);
                if (iB + 32 < n) b1 = __ldcs(dp + iB + 32);
                if (iB + 64 < n) b2 = __ldcs(dp + iB + 64);
                if (iB + 96 < n) b3 = __ldcs(dp + iB + 96);
            }

            if (iA < n)      lsum += doRow(a0, sDest[rowT],        op);
            if (iA + 32 < n) lsum += doRow(a1, sDest[rowT + 32],   op);
            if (iA + 64 < n) lsum += doRow(a2, sDest[rowT + 64],   op);
            if (iA + 96 < n) lsum += doRow(a3, sDest[rowT + 96],   op);
            if (hasB) {
                int rB = TILE + rowT;
                if (iB < n)      lsum += doRow(b0, sDest[rB],      op);
                if (iB + 32 < n) lsum += doRow(b1, sDest[rB + 32], op);
                if (iB + 64 < n) lsum += doRow(b2, sDest[rB + 64], op);
                if (iB + 96 < n) lsum += doRow(b3, sDest[rB + 96], op);
            }
        }

        // ---- analytic sorted-label fill for both tiles -------------------
        {
            int p = tileA * TILE + tid * 4;
#pragma unroll
            for (int t = 0; t < 2; ++t) {
                if (t == 1 && !hasB) break;
                int q = p + t * TILE;
                if (q < n) {
                    float4 o;
                    o.x = (float)((q     >= cb.y) + (q     >= cb.z) + (q     >= cb.w));
                    o.y = (float)((q + 1 >= cb.y) + (q + 1 >= cb.z) + (q + 1 >= cb.w));
                    o.z = (float)((q + 2 >= cb.y) + (q + 2 >= cb.z) + (q + 2 >= cb.w));
                    o.w = (float)((q + 3 >= cb.y) + (q + 3 >= cb.z) + (q + 3 >= cb.w));
                    __stcs(reinterpret_cast<float4*>(outLabel) + (q >> 2), o);
                }
            }
        }

        cur = hasB ? add4(curB, sTileHist[s + 1]) : curB;
        __syncwarp();   // protect sDest reuse next super-tile (warp-private)
    }

    // ---------------- loss reduce + final scalar ----------------------------
#pragma unroll
    for (int off = 16; off > 0; off >>= 1)
        lsum += __shfl_down_sync(0xffffffffu, lsum, off);
    if (lane == 0) warpLoss[w] = lsum;
    __syncthreads();
    if (tid == 0) {
        double sum = 0.0;
#pragma unroll
        for (int ww = 0; ww < WPB; ++ww) sum += (double)warpLoss[ww];
        atomicAdd(&g_loss, sum);
    }

    __threadfence();
    __shared__ bool isLast;
    if (tid == 0) {
        unsigned t = atomicAdd(&g_scatDone, 1u);
        isLast = (t == gridDim.x - 1);
    }
    __syncthreads();
    if (isLast && tid == 0) {
        g_scatDone = 0;
        g_flag = 0;                                  // reset for next replay
        double L = *((volatile double*)&g_loss);
        outLoss[0] = (float)(L / (double)n);
    }
}

extern "C" void kernel_launch(void* const* d_in, const int* in_sizes, int n_in,
                              void* d_out, int out_size) {
    const float* data = (const float*)d_in[0];
    const int* label = (const int*)d_in[1];
    float* out = (float*)d_out;
    int n = in_sizes[1];

    int sms = 148;
    cudaDeviceGetAttribute(&sms, cudaDevAttrMultiProcessorCount, 0);

    int numTiles = (n + TILE - 1) / TILE;
    int grid = sms * RESIDENT_BPSM;
    if (grid > numTiles) grid = numTiles;
    int minGrid = (numTiles + T_PB_MAX - 1) / T_PB_MAX;
    if (grid < minGrid) grid = minGrid;
    if (grid > MAX_BLOCKS_G) grid = MAX_BLOCKS_G;

    fusedKernel<<<grid, TPB>>>(data, label, out, out + (size_t)n * 4,
                               out + (size_t)n * 5, n, numTiles);
}

// round 17
// speedup vs baseline: 1.0185x; 1.0185x over previous
#include <cuda_runtime.h>
#include <cuda_bf16.h>

// Single persistent kernel: stable 4-class counting sort + margin adjust +
// fused mean-NLL loss. Output: [data[N,4] | labels[N] | loss] float32.
//
// R17 = R15 (best measured: 6 blocks/SM x MLP-4, block-level scan) +
// precomputed per-warp prefix histograms: phase 2's rank stage reads ONE
// int4 from smem instead of re-summing up to 7 warp hists per tile.

constexpr int TPB = 256;
constexpr int WPB = 8;
constexpr int TILE = 1024;             // rows per tile
constexpr int T_PB_MAX = 12;
constexpr int MAX_BLOCKS_G = 4096;
constexpr int RESIDENT_BPSM = 6;

__device__ int4 g_blockHist[MAX_BLOCKS_G];
__device__ int4 g_blockOff[MAX_BLOCKS_G];
__device__ int4 g_classBase;
__device__ double g_loss;
__device__ unsigned g_histDone;
__device__ unsigned g_scatDone;
__device__ volatile unsigned g_flag;

static __device__ __forceinline__ int4 add4(int4 a, int4 b) {
    return make_int4(a.x + b.x, a.y + b.y, a.z + b.z, a.w + b.w);
}

__global__ void __launch_bounds__(TPB, RESIDENT_BPSM)
fusedKernel(const float* __restrict__ data, const int* __restrict__ label,
            float* __restrict__ outData, float* __restrict__ outLabel,
            float* __restrict__ outLoss, int n, int numTiles) {
    __shared__ unsigned char sClass[T_PB_MAX][TILE / 4];  // 2 bits/row packed
    __shared__ int4 sWarpHist[T_PB_MAX][WPB];
    __shared__ int4 sWarpPre[T_PB_MAX][WPB];              // exclusive prefixes
    __shared__ int4 sTileHist[T_PB_MAX];
    __shared__ int sDest[TILE];                           // (dest<<2)|class
    __shared__ float warpLoss[WPB];
    __shared__ bool sScan;

    int tid = threadIdx.x;
    int w = tid >> 5;
    int lane = tid & 31;

    int t0 = (int)(((long long)blockIdx.x * numTiles) / gridDim.x);
    int t1 = (int)(((long long)(blockIdx.x + 1) * numTiles) / gridDim.x);
    int nt = t1 - t0;
    int nv4 = n >> 2;

    // ---------------- Phase 1: labels -> smem classes + hists ---------------
    for (int s = 0; s < nt; ++s) {
        int tile = t0 + s;
        int vi = (tile * (TILE / 4)) + tid;          // rows 4vi..4vi+3
        int c0 = 0, c1 = 0, c2 = 0, c3 = 0;
        unsigned byte = 0;
        if (vi < nv4) {
            int4 L = __ldcs(reinterpret_cast<const int4*>(label) + vi);
            byte = (unsigned)(L.x | (L.y << 2) | (L.z << 4) | (L.w << 6));
            c0 = (L.x == 0) + (L.y == 0) + (L.z == 0) + (L.w == 0);
            c1 = (L.x == 1) + (L.y == 1) + (L.z == 1) + (L.w == 1);
            c2 = (L.x == 2) + (L.y == 2) + (L.z == 2) + (L.w == 2);
            c3 = (L.x == 3) + (L.y == 3) + (L.z == 3) + (L.w == 3);
        }
        sClass[s][tid] = (unsigned char)byte;
#pragma unroll
        for (int off = 16; off > 0; off >>= 1) {
            c0 += __shfl_down_sync(0xffffffffu, c0, off);
            c1 += __shfl_down_sync(0xffffffffu, c1, off);
            c2 += __shfl_down_sync(0xffffffffu, c2, off);
            c3 += __shfl_down_sync(0xffffffffu, c3, off);
        }
        if (lane == 0) sWarpHist[s][w] = make_int4(c0, c1, c2, c3);
    }
    __syncthreads();
    // per-(tile,warp) exclusive prefixes + per-tile totals (one tiny pass)
    if (tid < nt * WPB) {
        int s = tid >> 3, ww = tid & 7;
        int4 p = make_int4(0, 0, 0, 0);
        for (int j = 0; j < ww; ++j) p = add4(p, sWarpHist[s][j]);
        sWarpPre[s][ww] = p;
        if (ww == WPB - 1) sTileHist[s] = add4(p, sWarpHist[s][ww]);
    }
    __syncthreads();
    if (tid == 0) {                                  // per-BLOCK total
        int4 bsum = make_int4(0, 0, 0, 0);
        for (int s = 0; s < nt; ++s) bsum = add4(bsum, sTileHist[s]);
        g_blockHist[blockIdx.x] = bsum;
    }

    // ---------------- Grid sync + block-level scan by last block ------------
    __threadfence();
    if (tid == 0) {
        unsigned t = atomicAdd(&g_histDone, 1u);
        sScan = (t == gridDim.x - 1);
        if (sScan) g_histDone = 0;                   // reset for graph replay
    }
    __syncthreads();

    if (sScan) {
        __shared__ int4 ss[TPB];
        int numB = gridDim.x;
        int chunk = (numB + TPB - 1) / TPB;
        int start = tid * chunk;
        int end = min(start + chunk, numB);
        int4 s = make_int4(0, 0, 0, 0);
        for (int j = start; j < end; ++j) s = add4(s, g_blockHist[j]);
        ss[tid] = s;
        __syncthreads();
        for (int off = 1; off < TPB; off <<= 1) {
            int4 v = ss[tid];
            if (tid >= off) v = add4(v, ss[tid - off]);
            __syncthreads();
            ss[tid] = v;
            __syncthreads();
        }
        int4 incl = ss[tid];
        int4 tot = ss[TPB - 1];
        int4 run;
        run.x = (incl.x - s.x);
        run.y = (incl.y - s.y) + tot.x;
        run.z = (incl.z - s.z) + tot.x + tot.y;
        run.w = (incl.w - s.w) + tot.x + tot.y + tot.z;
        for (int j = start; j < end; ++j) {
            int4 h = g_blockHist[j];
            g_blockOff[j] = run;
            run = add4(run, h);
        }
        if (tid == 0) {
            g_classBase = make_int4(0, tot.x, tot.x + tot.y,
                                    tot.x + tot.y + tot.z);
            g_loss = 0.0;
        }
        __syncthreads();
        __threadfence();
        if (tid == 0) g_flag = 1;                    // release
    } else {
        if (tid == 0) {
            while (g_flag == 0) __nanosleep(64);
        }
        __syncthreads();
        __threadfence();                             // acquire
    }

    // ---------------- Phase 2: rank via packed scan, coalesced scatter ------
    int4 cb = g_classBase;
    int4 cur = g_blockOff[blockIdx.x];               // running tile offsets
    float lsum = 0.0f;

    for (int s = 0; s < nt; ++s) {
        int tile = t0 + s;

        // ---- rank this thread's 4 consecutive rows (rows 4*tid..4*tid+3) ---
        {
            int4 pre = sWarpPre[s][w];               // one LDS.128
            int base0 = cur.x + pre.x, base1 = cur.y + pre.y;
            int base2 = cur.z + pre.z, base3 = cur.w + pre.w;

            unsigned byte = sClass[s][tid];
            int c0 = byte & 3, c1 = (byte >> 2) & 3;
            int c2 = (byte >> 4) & 3, c3 = (byte >> 6) & 3;
            unsigned cnt = (1u << (8 * c0)) + (1u << (8 * c1)) +
                           (1u << (8 * c2)) + (1u << (8 * c3));
            unsigned incl = cnt;
#pragma unroll
            for (int off = 1; off < 32; off <<= 1) {
                unsigned v = __shfl_up_sync(0xffffffffu, incl, off);
                if (lane >= off) incl += v;
            }
            unsigned excl = incl - cnt;
            base0 += excl & 0xff;
            base1 += (excl >> 8) & 0xff;
            base2 += (excl >> 16) & 0xff;
            base3 += (excl >> 24) & 0xff;

            int4 dpk;
            int* dv = &dpk.x;
#pragma unroll
            for (int k = 0; k < 4; ++k) {
                int c = (k == 0) ? c0 : (k == 1) ? c1 : (k == 2) ? c2 : c3;
                int dest;
                if (c == 0) dest = base0++;
                else if (c == 1) dest = base1++;
                else if (c == 2) dest = base2++;
                else dest = base3++;
                dv[k] = (dest << 2) | c;
            }
            reinterpret_cast<int4*>(sDest)[tid] = dpk;
        }
        __syncwarp();

        // ---- coalesced streaming loads (MLP=4) + process + scatter ----------
        {
            int rowT = w * 128 + lane;
            int idx0 = tile * TILE + rowT;
            const float4* dp = reinterpret_cast<const float4*>(data);

            float4 r0, r1, r2, r3;
            r0 = r1 = r2 = r3 = make_float4(0.f, 0.f, 0.f, 0.f);
            if (idx0 < n)       r0 = __ldcs(dp + idx0);
            if (idx0 + 32 < n)  r1 = __ldcs(dp + idx0 + 32);
            if (idx0 + 64 < n)  r2 = __ldcs(dp + idx0 + 64);
            if (idx0 + 96 < n)  r3 = __ldcs(dp + idx0 + 96);

            int d0 = sDest[rowT], d1 = sDest[rowT + 32];
            int d2 = sDest[rowT + 64], d3 = sDest[rowT + 96];

#pragma unroll
            for (int k = 0; k < 4; ++k) {
                if (idx0 + k * 32 >= n) break;
                float4 r = (k == 0) ? r0 : (k == 1) ? r1 : (k == 2) ? r2 : r3;
                int dpacked = (k == 0) ? d0 : (k == 1) ? d1
                            : (k == 2) ? d2 : d3;
                int c = dpacked & 3;
                int dest = dpacked >> 2;

                float v = (c == 0) ? r.x : (c == 1) ? r.y
                        : (c == 2) ? r.z : r.w;
                float adj = (v > 0.0f) ? v * (1.0f / 4.00001f) - 0.5f
                                       : v * 4.00001f - 0.5f;
                if (c == 0) r.x = adj; else if (c == 1) r.y = adj;
                else if (c == 2) r.z = adj; else r.w = adj;

                // no max-subtraction: inputs ~N(0,1) -> exp cannot overflow
                float e = __expf(r.x) + __expf(r.y) +
                          __expf(r.z) + __expf(r.w);
                lsum += __logf(e) - adj;             // -log p[true]

                __stcs(reinterpret_cast<float4*>(outData) + dest, r);
            }
        }

        // ---- analytic sorted-label fill (streaming float4) ------------------
        {
            int p = tile * TILE + tid * 4;
            if (p < n) {
                float4 o;
                o.x = (float)((p     >= cb.y) + (p     >= cb.z) + (p     >= cb.w));
                o.y = (float)((p + 1 >= cb.y) + (p + 1 >= cb.z) + (p + 1 >= cb.w));
                o.z = (float)((p + 2 >= cb.y) + (p + 2 >= cb.z) + (p + 2 >= cb.w));
                o.w = (float)((p + 3 >= cb.y) + (p + 3 >= cb.z) + (p + 3 >= cb.w));
                __stcs(reinterpret_cast<float4*>(outLabel) + (p >> 2), o);
            }
        }

        cur = add4(cur, sTileHist[s]);               // advance to next tile
        __syncwarp();   // protect sDest reuse next tile (warp-private region)
    }

    // ---------------- loss reduce + final scalar ----------------------------
#pragma unroll
    for (int off = 16; off > 0; off >>= 1)
        lsum += __shfl_down_sync(0xffffffffu, lsum, off);
    if (lane == 0) warpLoss[w] = lsum;
    __syncthreads();
    if (tid == 0) {
        double sum = 0.0;
#pragma unroll
        for (int ww = 0; ww < WPB; ++ww) sum += (double)warpLoss[ww];
        atomicAdd(&g_loss, sum);
    }

    __threadfence();
    __shared__ bool isLast;
    if (tid == 0) {
        unsigned t = atomicAdd(&g_scatDone, 1u);
        isLast = (t == gridDim.x - 1);
    }
    __syncthreads();
    if (isLast && tid == 0) {
        g_scatDone = 0;
        g_flag = 0;                                  // reset for next replay
        double L = *((volatile double*)&g_loss);
        outLoss[0] = (float)(L / (double)n);
    }
}

extern "C" void kernel_launch(void* const* d_in, const int* in_sizes, int n_in,
                              void* d_out, int out_size) {
    const float* data = (const float*)d_in[0];
    const int* label = (const int*)d_in[1];
    float* out = (float*)d_out;
    int n = in_sizes[1];

    int sms = 148;
    cudaDeviceGetAttribute(&sms, cudaDevAttrMultiProcessorCount, 0);

    int numTiles = (n + TILE - 1) / TILE;
    int grid = sms * RESIDENT_BPSM;
    if (grid > numTiles) grid = numTiles;
    int minGrid = (numTiles + T_PB_MAX - 1) / T_PB_MAX;
    if (grid < minGrid) grid = minGrid;
    if (grid > MAX_BLOCKS_G) grid = MAX_BLOCKS_G;

    fusedKernel<<<grid, TPB>>>(data, label, out, out + (size_t)n * 4,
                               out + (size_t)n * 5, n, numTiles);
}